// round 7
// baseline (speedup 1.0000x reference)
#include <cuda_runtime.h>

// ---------------------------------------------------------------------------
// EResidualBlockBucket: x -> grouped3x3+ReLU -> per-pixel bucket-indexed
// dynamic 3x3 conv (+per-pixel bias) -> ReLU -> 1x1 conv -> +x -> ReLU
//
// R6 profile of k_dyn: 66.9us, ALL pipes <50% (L1 48.6, fma 13.6, alu 12.5,
// issue 29) -> stall-bound on per-icc stage->barrier->compute serialization.
// R7: double-buffered ws/ps in 64KB dynamic smem (2 CTAs/SM kept on B200's
// 227KB), weights staged via cp.async (latency hidden behind compute), one
// barrier per icc instead of two, all div/mod address math hoisted out of
// the hot loop (computed once per thread / incrementally).
// ---------------------------------------------------------------------------

#define HPW 66                 // padded image width/height
#define HPSZ (64 * HPW * HPW)  // h_pad elements: [y][x][ic], ic fastest

// Zero-initialized at module load; k_gconv overwrites the interior each call,
// the 1-px halo border is never written -> stays zero (SAME padding).
__device__ __align__(16) float g_hpad[HPSZ];     // padded h, pixel-major

typedef unsigned long long ull;

__device__ __forceinline__ void ffma2(ull& d, ull a, ull b) {
    asm("fma.rn.f32x2 %0, %1, %2, %0;" : "+l"(d) : "l"(a), "l"(b));
}
__device__ __forceinline__ ull pack2(float v) {
    ull r; asm("mov.b64 %0, {%1, %1};" : "=l"(r) : "f"(v)); return r;
}
__device__ __forceinline__ ull packf(float lo, float hi) {
    ull r; asm("mov.b64 %0, {%1, %2};" : "=l"(r) : "f"(lo), "f"(hi)); return r;
}
__device__ __forceinline__ float2 unpack2(ull v) {
    float2 r; asm("mov.b64 {%0, %1}, %2;" : "=f"(r.x), "=f"(r.y) : "l"(v));
    return r;
}
__device__ __forceinline__ void cp4(unsigned dst, const float* src) {
    asm volatile("cp.async.ca.shared.global [%0], [%1], 4;"
                 :: "r"(dst), "l"(src));
}
#define CP_COMMIT() asm volatile("cp.async.commit_group;")
#define CP_WAIT0()  asm volatile("cp.async.wait_group 0;" ::: "memory")

// dynamic smem layout (bytes), all 16B aligned
#define SM_WS0 0
#define SM_WS1 18432
#define SM_PS0 36864
#define SM_PS1 (36864 + 9504)
#define SM_PL  (36864 + 19008)           // plist: 4096 ushort
#define SM_TOT (SM_PL + 8192)            // 64064 B

// ---------------- K1: grouped 3x3 conv + bias + ReLU -> g_hpad -------------
__global__ void __launch_bounds__(256) k_gconv(const float* __restrict__ x,
                                               const float* __restrict__ w1,
                                               const float* __restrict__ b1) {
    __shared__ float xs[16][18][18];
    __shared__ float ws[16][144];
    __shared__ float bs[16];

    int bx = blockIdx.x;
    int g = bx >> 4;
    int tile = bx & 15;
    int y0 = (tile >> 2) * 16, x0 = (tile & 3) * 16;
    int tid = threadIdx.x;

    for (int i = tid; i < 16 * 18 * 18; i += 256) {
        int ic = i / 324;
        int rem = i - ic * 324;
        int r = rem / 18, c = rem - r * 18;
        int yy = y0 - 1 + r, xx = x0 - 1 + c;
        float v = 0.f;
        if (yy >= 0 && yy < 64 && xx >= 0 && xx < 64)
            v = x[(g * 16 + ic) * 4096 + yy * 64 + xx];
        xs[ic][r][c] = v;
    }
    for (int i = tid; i < 16 * 144; i += 256) {
        int oc = i / 144;
        ws[oc][i - oc * 144] = w1[(g * 16 + oc) * 144 + (i - oc * 144)];
    }
    if (tid < 16) bs[tid] = b1[g * 16 + tid];
    __syncthreads();

    int r = tid >> 4, c = tid & 15;
    float acc[16];
#pragma unroll
    for (int j = 0; j < 16; ++j) acc[j] = bs[j];

    for (int ic = 0; ic < 16; ++ic) {
        float p[9];
#pragma unroll
        for (int dy = 0; dy < 3; ++dy)
#pragma unroll
            for (int dx = 0; dx < 3; ++dx)
                p[dy * 3 + dx] = xs[ic][r + dy][c + dx];
#pragma unroll
        for (int j = 0; j < 16; ++j) {
#pragma unroll
            for (int k = 0; k < 9; ++k)
                acc[j] = fmaf(ws[j][ic * 9 + k], p[k], acc[j]);
        }
    }
    float* dst = g_hpad + (((y0 + r + 1) * HPW) + (x0 + c + 1)) * 64 + g * 16;
#pragma unroll
    for (int j = 0; j < 16; ++j) dst[j] = fmaxf(acc[j], 0.f);
}

// ---------------- K2: bucket-grouped dynamic conv + fused epilogue ---------
// grid 216 x 512 threads (16 warps, warp w -> ocs [4w,4w+4) as f32x2 pairs),
// lanes = pixel slots. Double-buffered icc pipeline, cp.async weights.
__global__ void __launch_bounds__(512, 2)
k_dyn(const int* __restrict__ buckets, const float* __restrict__ emb,
      const float* __restrict__ x, const float* __restrict__ w2,
      const float* __restrict__ b2, float* __restrict__ out) {
    extern __shared__ __align__(16) char sm[];
    float* wsb[2] = { (float*)(sm + SM_WS0), (float*)(sm + SM_WS1) };
    float* psb[2] = { (float*)(sm + SM_PS0), (float*)(sm + SM_PS1) };
    unsigned short* plist = (unsigned short*)(sm + SM_PL);
    __shared__ int s_count;

    unsigned smbase = (unsigned)__cvta_generic_to_shared(sm);
    unsigned wsb_sm[2] = { smbase + SM_WS0, smbase + SM_WS1 };

    int t = blockIdx.x;
    int tid = threadIdx.x;
    if (tid == 0) s_count = 0;
    __syncthreads();
    for (int i = tid; i < 4096; i += 512) {
        if (buckets[i] == t) {
            int p = atomicAdd(&s_count, 1);
            plist[p] = (unsigned short)i;
        }
    }
    __syncthreads();
    int n = s_count;
    if (n == 0) return;

    int lane = tid & 31;
    int wid = tid >> 5;               // 0..15
    int oc_base = wid * 4;
    const float* W = emb + (size_t)t * 36928;

    // ---- per-thread invariant staging indices (no div/mod in hot loop) ----
    // patch item A (all threads): t2 = tid; item B (tid<64): t2 = tid+512
    int qA = tid & 1;
    int rA = tid >> 1;                 // 0..255
    int slotA = rA / 9, posA = rA - slotA * 9;
    int dyA = posA / 3, dxA = posA - dyA * 3;
    int psA = (qA * 4 * 9 + posA) * 33 + slotA;     // +k*297 for ic k
    int gpA = (dyA * HPW + dxA) * 64 + qA * 4;      // + (y*66+x)*64 + icc
    int rB = rA + 256;                               // 256..287 (tid<64)
    int slotB = rB / 9, posB = rB - slotB * 9;
    int dyB = posB / 3, dxB = posB - dyB * 3;
    int psB = (qA * 4 * 9 + posB) * 33 + slotB;
    int gpB = (dyB * HPW + dxB) * 64 + qA * 4;
    // weights: 9 items, incremental oc/cl/goff from one initial div
    int w_oc0 = tid / 72;
    int w_cl0 = tid - w_oc0 * 72;
    int w_go0 = w_oc0 * 577 + w_cl0;

    for (int chunk = 0; chunk < n; chunk += 32) {
        int pi = chunk + lane;
        int mypix = plist[pi < n ? pi : n - 1];

        // chunk-dependent patch gmem bases
        int pjA = chunk + slotA;
        int pxA = plist[pjA < n ? pjA : n - 1];
        int gA = ((pxA >> 6) * HPW + (pxA & 63)) * 64 + gpA;
        int pjB = chunk + slotB;
        int pxB = plist[pjB < n ? pjB : n - 1];
        int gB = ((pxB >> 6) * HPW + (pxB & 63)) * 64 + gpB;

        ull acc2[2];
        acc2[0] = packf(__ldg(W + (oc_base + 0) * 577 + 576),
                        __ldg(W + (oc_base + 1) * 577 + 576));
        acc2[1] = packf(__ldg(W + (oc_base + 2) * 577 + 576),
                        __ldg(W + (oc_base + 3) * 577 + 576));

        // ---- staging lambdas (inlined by compiler) ----
        auto stage_w = [&](int icc8, unsigned dstb) {
            const float* Wi = W + icc8 * 72;
            int oc = w_oc0, cl = w_cl0, go = w_go0;
#pragma unroll
            for (int k = 0; k < 9; ++k) {
                unsigned d = dstb +
                    (((oc >> 1) * 144 + cl * 2 + (oc & 1)) << 2);
                cp4(d, Wi + go);
                oc += 7; cl += 8; go += 4047;
                if (cl >= 72) { cl -= 72; ++oc; go += 505; }
            }
        };
        auto stage_p = [&](int icc8, float* ps) {
            int icc = icc8 * 8;
            {
                float4 v = *(const float4*)(g_hpad + gA + icc);
                ps[psA + 0]   = v.x;
                ps[psA + 297] = v.y;
                ps[psA + 594] = v.z;
                ps[psA + 891] = v.w;
            }
            if (tid < 64) {
                float4 v = *(const float4*)(g_hpad + gB + icc);
                ps[psB + 0]   = v.x;
                ps[psB + 297] = v.y;
                ps[psB + 594] = v.z;
                ps[psB + 891] = v.w;
            }
        };

        // ---- prologue: stage icc 0 into buffer 0 ----
        stage_w(0, wsb_sm[0]);
        CP_COMMIT();
        stage_p(0, psb[0]);
        CP_WAIT0();
        __syncthreads();

        for (int icc8 = 0; icc8 < 8; ++icc8) {
            int cur = icc8 & 1, nx = cur ^ 1;
            if (icc8 < 7) {
                stage_w(icc8 + 1, wsb_sm[nx]);
                CP_COMMIT();
                stage_p(icc8 + 1, psb[nx]);
            }
            // ---- compute from [cur]: 72 c x 2 oc-pairs per warp, FFMA2
            const float* psl = psb[cur] + lane;
            const ulonglong2* wp0 =
                ((const ulonglong2*)wsb[cur]) + (2 * wid) * 36;
            const ulonglong2* wp1 = wp0 + 36;
#pragma unroll
            for (int c4 = 0; c4 < 72; c4 += 4) {
                ull p0 = pack2(psl[(c4 + 0) * 33]);
                ull p1 = pack2(psl[(c4 + 1) * 33]);
                ull p2 = pack2(psl[(c4 + 2) * 33]);
                ull p3 = pack2(psl[(c4 + 3) * 33]);
                ulonglong2 a01 = wp0[(c4 >> 1)];
                ulonglong2 a23 = wp0[(c4 >> 1) + 1];
                ulonglong2 b01 = wp1[(c4 >> 1)];
                ulonglong2 b23 = wp1[(c4 >> 1) + 1];
                ffma2(acc2[0], a01.x, p0);
                ffma2(acc2[0], a01.y, p1);
                ffma2(acc2[0], a23.x, p2);
                ffma2(acc2[0], a23.y, p3);
                ffma2(acc2[1], b01.x, p0);
                ffma2(acc2[1], b01.y, p1);
                ffma2(acc2[1], b23.x, p2);
                ffma2(acc2[1], b23.y, p3);
            }
            CP_WAIT0();
            __syncthreads();
        }

        // ---- fused epilogue: ReLU -> 1x1 conv (w2) + b2 -> +x -> ReLU
        float* ds = psb[0];   // all ps/ws dead after final barrier
        float2 r01 = unpack2(acc2[0]);
        float2 r23 = unpack2(acc2[1]);
        ds[(oc_base + 0) * 33 + lane] = fmaxf(r01.x, 0.f);
        ds[(oc_base + 1) * 33 + lane] = fmaxf(r01.y, 0.f);
        ds[(oc_base + 2) * 33 + lane] = fmaxf(r23.x, 0.f);
        ds[(oc_base + 3) * 33 + lane] = fmaxf(r23.y, 0.f);
        __syncthreads();

        float eacc[4];
#pragma unroll
        for (int j = 0; j < 4; ++j) eacc[j] = __ldg(b2 + oc_base + j);

#pragma unroll
        for (int blk = 0; blk < 4; ++blk) {
            float pv[16];
#pragma unroll
            for (int q = 0; q < 16; ++q)
                pv[q] = ds[(blk * 16 + q) * 33 + lane];
#pragma unroll
            for (int j = 0; j < 4; ++j) {
                const float4* wr = (const float4*)(w2 +
                    (oc_base + j) * 64 + blk * 16);
#pragma unroll
                for (int q4 = 0; q4 < 4; ++q4) {
                    float4 w = __ldg(wr + q4);
                    eacc[j] = fmaf(w.x, pv[q4 * 4 + 0], eacc[j]);
                    eacc[j] = fmaf(w.y, pv[q4 * 4 + 1], eacc[j]);
                    eacc[j] = fmaf(w.z, pv[q4 * 4 + 2], eacc[j]);
                    eacc[j] = fmaf(w.w, pv[q4 * 4 + 3], eacc[j]);
                }
            }
        }

        if (pi < n) {
#pragma unroll
            for (int j = 0; j < 4; ++j) {
                int o = oc_base + j;
                out[o * 4096 + mypix] =
                    fmaxf(eacc[j] + __ldg(x + o * 4096 + mypix), 0.f);
            }
        }
        __syncthreads();   // ds (= ps0) must drain before next chunk stages
    }
}

// ---------------------------------------------------------------------------
extern "C" void kernel_launch(void* const* d_in, const int* in_sizes, int n_in,
                              void* d_out, int out_size) {
    const float* x       = (const float*)d_in[0];
    const int*   buckets = (const int*)  d_in[1];
    const float* w1      = (const float*)d_in[2];
    const float* b1      = (const float*)d_in[3];
    const float* emb     = (const float*)d_in[4];
    const float* w2      = (const float*)d_in[5];
    const float* b2      = (const float*)d_in[6];
    float* out = (float*)d_out;

    // host-side attribute set (not a stream op; graph-capture safe, idempotent)
    cudaFuncSetAttribute(k_dyn, cudaFuncAttributeMaxDynamicSharedMemorySize,
                         SM_TOT);

    k_gconv<<<64, 256>>>(x, w1, b1);
    k_dyn<<<216, 512, SM_TOT>>>(buckets, emb, x, w2, b2, out);
}